// round 14
// baseline (speedup 1.0000x reference)
#include <cuda_runtime.h>

// PoseLSTM v13: v12 + corrected anti-phase (350cyc) + in-warp MUFU/FMA interleave.
//   256 blocks x 400 threads, 2 blocks/SM. Second CTA (bid>=148) staggers by
//   ~350cyc (half the DE-PHASED step, not half the aligned step).
//   Step body ordered matvec(A); act(A); matvec(B); act(B) so ~4 MUFUs fly
//   under the second element's FMA burst inside each warp.
//   thread = (l, u, eh, gp): 2 gate rows (i,f | g,o) for elements eh, eh+2,
//   finishes the CELL of only ITS element; 2 shfl.xor(1) exchange.

#define T_ 1024
#define B_ 1024
#define L_ 10
#define H_ 10
#define NB 4
#define NTH 400

typedef unsigned long long u64;

template <bool B> struct BoolC { static constexpr bool value = B; };

__device__ __forceinline__ u64 pk2(float lo, float hi) {
    u64 r; asm("mov.b64 %0, {%1,%2};" : "=l"(r) : "f"(lo), "f"(hi)); return r;
}
__device__ __forceinline__ void upk2(u64 v, float& lo, float& hi) {
    asm("mov.b64 {%0,%1}, %2;" : "=f"(lo), "=f"(hi) : "l"(v));
}
__device__ __forceinline__ u64 fma2(u64 a, u64 b, u64 c) {
    u64 d; asm("fma.rn.f32x2 %0, %1, %2, %3;" : "=l"(d) : "l"(a), "l"(b), "l"(c));
    return d;
}
__device__ __forceinline__ u64 mul2(u64 a, u64 b) {
    u64 d; asm("mul.rn.f32x2 %0, %1, %2;" : "=l"(d) : "l"(a), "l"(b));
    return d;
}
__device__ __forceinline__ u64 add2(u64 a, u64 b) {
    u64 d; asm("add.rn.f32x2 %0, %1, %2;" : "=l"(d) : "l"(a), "l"(b));
    return d;
}
__device__ __forceinline__ float tanhap(float x) {
    float r; asm("tanh.approx.f32 %0, %1;" : "=f"(r) : "f"(x)); return r;
}

// matvec for one element: 2 gate rows, 4 chains, bias pre-folded
__device__ __forceinline__ void matvec2(const ulonglong2* zz,
                                        const u64* wA, const u64* wB,
                                        u64 biasA2, u64 biasB2,
                                        float& pA, float& pB) {
    ulonglong2 v0 = zz[0], v1 = zz[1], v2 = zz[2], v3 = zz[3], v4 = zz[4];
    u64 a  = fma2(wA[0], v0.x, biasA2);
    u64 a_ = mul2(wA[1], v0.y);
    u64 b  = fma2(wB[0], v0.x, biasB2);
    u64 b_ = mul2(wB[1], v0.y);
    a  = fma2(wA[2], v1.x, a);  a_ = fma2(wA[3], v1.y, a_);
    b  = fma2(wB[2], v1.x, b);  b_ = fma2(wB[3], v1.y, b_);
    a  = fma2(wA[4], v2.x, a);  a_ = fma2(wA[5], v2.y, a_);
    b  = fma2(wB[4], v2.x, b);  b_ = fma2(wB[5], v2.y, b_);
    a  = fma2(wA[6], v3.x, a);  a_ = fma2(wA[7], v3.y, a_);
    b  = fma2(wB[6], v3.x, b);  b_ = fma2(wB[7], v3.y, b_);
    a  = fma2(wA[8], v4.x, a);  a_ = fma2(wA[9], v4.y, a_);
    b  = fma2(wB[8], v4.x, b);  b_ = fma2(wB[9], v4.y, b_);
    u64 sA = add2(a, a_), sB = add2(b, b_);
    float lo, hi;
    upk2(sA, lo, hi); pA = lo + hi;
    upk2(sB, lo, hi); pB = lo + hi;
}

__global__ __launch_bounds__(NTH, 2)
void lstm_pipe13(const float* __restrict__ x,   // (T,B,H)
                 const float* __restrict__ hp,  // (L,B,H)
                 const float* __restrict__ cp,  // (L,B,H)
                 const float* __restrict__ Wih, // (L,4H,H)
                 const float* __restrict__ Whh, // (L,4H,H)
                 const float* __restrict__ bih, // (L,4H)
                 const float* __restrict__ bhh, // (L,4H)
                 float* __restrict__ out)       // ys ++ hn ++ cn
{
    // z[buf][layer][elem(4)][24]: 0..9 input-from-below, 10..19 own h.
    __shared__ __align__(16) float z[2][L_ + 1][NB][24];

    // anti-phase: second CTA on each SM, offset = half the DE-PHASED step
    if (blockIdx.x >= 148) {
        long long t0 = clock64();
        while ((long long)(clock64() - t0) < 350LL) {}
    }

    const int tid = threadIdx.x;
    const int l   = tid / 40;
    const int r   = tid % 40;          // u*4 + eh*2 + gp
    const int u   = r >> 2;
    const int eh  = (r >> 1) & 1;      // element slots eh and eh+2
    const int gp  = r & 1;             // 0: rows (i,f)  1: rows (g~,o)
    const int e2  = eh + 2;
    const int em  = gp ? e2 : eh;      // the element THIS lane finishes
    const int bm  = blockIdx.x * NB + em;

    // ---- k-packed register-stationary weights, sigmoid 0.5 folded ----
    const int rowA = l * 40 + gp * 20 + u;    // i (gp0) or g~ (gp1)
    const int rowB = rowA + 10;               // f (gp0) or o  (gp1)
    const float sclA = gp ? 1.0f : 0.5f;
    u64 wA[10], wB[10];
    {
        const float* WiA = Wih + rowA * 10; const float* WhA = Whh + rowA * 10;
        const float* WiB = Wih + rowB * 10; const float* WhB = Whh + rowB * 10;
#pragma unroll
        for (int k = 0; k < 5; ++k) {
            wA[k]     = pk2(sclA * __ldg(WiA + 2 * k), sclA * __ldg(WiA + 2 * k + 1));
            wA[5 + k] = pk2(sclA * __ldg(WhA + 2 * k), sclA * __ldg(WhA + 2 * k + 1));
            wB[k]     = pk2(0.5f * __ldg(WiB + 2 * k), 0.5f * __ldg(WiB + 2 * k + 1));
            wB[5 + k] = pk2(0.5f * __ldg(WhB + 2 * k), 0.5f * __ldg(WhB + 2 * k + 1));
        }
    }
    const u64 biasA2 = pk2(sclA * (bih[rowA] + bhh[rowA]), 0.0f);
    const u64 biasB2 = pk2(0.5f * (bih[rowB] + bhh[rowB]), 0.0f);
    const float cAa = gp ? 0.0f : 0.5f;   // act A: gp0 sigmoid, gp1 tanh
    const float cBa = gp ? 1.0f : 0.5f;

    // ---- init state (one element per lane) ----
    float cm = cp[(l * B_ + bm) * H_ + u];
    z[l & 1][l][em][10 + u] = hp[(l * B_ + bm) * H_ + u];
    const bool isLdr = (l == 0);
    if (isLdr)
        z[0][0][em][u] = x[(size_t)bm * H_ + u];

    const size_t base_hn = (size_t)T_ * B_ * H_;
    const size_t base_cn = base_hn + (size_t)L_ * B_ * H_;

    // ---- one wavefront step (ST = steady: no guards, no tail checks) ----
    auto stepf = [&](int scur, int par, auto SC) {
        constexpr bool ST = decltype(SC)::value;
        const int t = scur - l;
        const bool act = ST ? true : ((unsigned)t < (unsigned)T_);

        float xl;
        const bool ldrGo = isLdr && (ST ? true : (scur + 1 < T_));
        if (ldrGo)
            xl = x[((size_t)(scur + 1) * B_ + bm) * H_ + u];

        __syncthreads();   // step s-1 z-writes -> step s z-reads

        const ulonglong2* zzA =
            reinterpret_cast<const ulonglong2*>(&z[par][l][eh][0]);
        const ulonglong2* zzB =
            reinterpret_cast<const ulonglong2*>(&z[par][l][e2][0]);

        // element A: matvec then IMMEDIATELY its MUFUs (fly under B's FMAs)
        float pA, pB;
        matvec2(zzA, wA, wB, biasA2, biasB2, pA, pB);
        float vA = fmaf(cBa,  tanhap(pA), cAa);   // eh gateA (i | g~)
        float vB = fmaf(0.5f, tanhap(pB), 0.5f);  // eh gateB (f | o)

        float qA, qB;
        matvec2(zzB, wA, wB, biasA2, biasB2, qA, qB);
        float vA2 = fmaf(cBa,  tanhap(qA), cAa);  // e2 gateA
        float vB2 = fmaf(0.5f, tanhap(qB), 0.5f); // e2 gateB

        // each lane keeps ITS element's gates, ships the other's
        float ownA = gp ? vA2 : vA;
        float ownB = gp ? vB2 : vB;
        float sndA = gp ? vA  : vA2;
        float sndB = gp ? vB  : vB2;
        float rcvA = __shfl_xor_sync(0xFFFFFFFFu, sndA, 1);
        float rcvB = __shfl_xor_sync(0xFFFFFFFFu, sndB, 1);
        float F = gp ? rcvB : ownB;
        float O = gp ? ownB : rcvB;
        if (act) cm = fmaf(F, cm, ownA * rcvA);
        float hm = O * tanhap(cm);

        if (act) {
            z[par ^ 1][l][em][10 + u] = hm;
            if (l < L_ - 1) {
                z[par ^ 1][l + 1][em][u] = hm;
            } else {
                out[((size_t)t * B_ + bm) * H_ + u] = hm;
            }
            if (!ST && t == T_ - 1) {
                out[base_hn + ((size_t)l * B_ + bm) * H_ + u] = hm;
                out[base_cn + ((size_t)l * B_ + bm) * H_ + u] = cm;
            }
        }
        if (ldrGo)
            z[par ^ 1][0][em][u] = xl;
    };

    // ---- ramp-up: s = 0..9 ----
    for (int s = 0; s < L_; ++s)
        stepf(s, s & 1, BoolC<false>{});

    // ---- steady: s = 10..1021, unrolled x4 ----
    for (int s0 = L_; s0 < T_ - 2; s0 += 4) {
        stepf(s0,     0, BoolC<true>{});
        stepf(s0 + 1, 1, BoolC<true>{});
        stepf(s0 + 2, 0, BoolC<true>{});
        stepf(s0 + 3, 1, BoolC<true>{});
    }

    // ---- ramp-down: s = 1022..1033 ----
    for (int s = T_ - 2; s < T_ + L_; ++s)
        stepf(s, s & 1, BoolC<false>{});
}

extern "C" void kernel_launch(void* const* d_in, const int* in_sizes, int n_in,
                              void* d_out, int out_size) {
    const float* x   = (const float*)d_in[0];
    const float* hp  = (const float*)d_in[1];
    const float* cp  = (const float*)d_in[2];
    const float* Wih = (const float*)d_in[3];
    const float* Whh = (const float*)d_in[4];
    const float* bih = (const float*)d_in[5];
    const float* bhh = (const float*)d_in[6];
    float* out = (float*)d_out;

    dim3 grid(B_ / NB);   // 256 blocks
    dim3 block(NTH);      // 400 threads
    lstm_pipe13<<<grid, block>>>(x, hp, cp, Wih, Whh, bih, bhh, out);
}